// round 13
// baseline (speedup 1.0000x reference)
#include <cuda_runtime.h>
#include <cuda_fp16.h>
#include <cstdint>

#define N_NODES 50000
#define FIN 512
#define FOUT 128
#define MAXE 1000000

// Static device scratch (no allocation anywhere):
__device__ __half g_pre[(size_t)N_NODES * FOUT];         // fp16 pre_sup, 12.8 MB
__device__ int   g_counts[2][N_NODES];
__device__ int   g_rowstart[2][N_NODES + 1];
__device__ int   g_cursor[2][N_NODES];
__device__ int2  g_edges[2][MAXE];                       // packed (col, val-bits)

// ---------------------------------------------------------------------------
// helpers
// ---------------------------------------------------------------------------
__device__ __forceinline__ uint32_t f2tf32(float f) {
    uint32_t u;
    asm("cvt.rna.tf32.f32 %0, %1;" : "=r"(u) : "f"(f));
    return u;
}

__device__ __forceinline__ void mma_tf32(float* d, const uint32_t* a, const uint32_t* b) {
    asm("mma.sync.aligned.m16n8k8.row.col.f32.tf32.tf32.f32 "
        "{%0,%1,%2,%3}, {%4,%5,%6,%7}, {%8,%9}, {%0,%1,%2,%3};"
        : "+f"(d[0]), "+f"(d[1]), "+f"(d[2]), "+f"(d[3])
        : "r"(a[0]), "r"(a[1]), "r"(a[2]), "r"(a[3]), "r"(b[0]), "r"(b[1]));
}

__device__ __forceinline__ uint32_t sptr(const void* p) {
    return (uint32_t)__cvta_generic_to_shared(p);
}

__device__ __forceinline__ void cp16(uint32_t s, const void* g, int src_sz) {
    asm volatile("cp.async.ca.shared.global [%0], [%1], 16, %2;"
                 :: "r"(s), "l"(g), "r"(src_sz));
}

// ---------------------------------------------------------------------------
// tf32 GEMM, cp.async double-buffered (R11-proven).
// g_pre[M, FOUT] (fp16) = A[M, FIN] * B[FIN, FOUT]
// Block tile M=128 x N=128, K-chunk 16, 2 stages, 256 threads = 8 warps.
// As[m][k] stride 20 / Bs[k][n] stride 136: conflict-free fragment reads.
// ---------------------------------------------------------------------------
#define GM 128
#define GK 16
#define ASTR 20
#define BSTR 136
#define NITER (FIN / GK)   // 32

__global__ __launch_bounds__(256, 2) void gemm_tf32_db(const float* __restrict__ A,
                                                       const float* __restrict__ B) {
    __shared__ float As[2][GM][ASTR];
    __shared__ float Bs[2][GK][BSTR];

    const int tid = threadIdx.x;
    const int w = tid >> 5, l = tid & 31;
    const int wm = (w >> 1) * 32;          // 4 warps over M
    const int wn = (w & 1) * 64;           // 2 warps over N
    const int g = l >> 2, tg = l & 3;
    const int block_row = blockIdx.x * GM;

    float acc[2][8][4];
#pragma unroll
    for (int mi = 0; mi < 2; mi++)
#pragma unroll
        for (int ni = 0; ni < 8; ni++)
#pragma unroll
            for (int q = 0; q < 4; q++) acc[mi][ni][q] = 0.f;

    const int am = tid >> 1;
    const int ak = (tid & 1) * 8;
    const int arow = block_row + am;
    const int asz = (arow < N_NODES) ? 16 : 0;     // zero-fill M tail
    const float* aG = A + (size_t)arow * FIN + ak;
    const int bk = tid >> 4;
    const int bn = (tid & 15) * 8;
    const float* bG = B + (size_t)bk * FOUT + bn;

    const uint32_t sA0 = sptr(&As[0][am][ak]);
    const uint32_t sA1 = sptr(&As[1][am][ak]);
    const uint32_t sB0 = sptr(&Bs[0][bk][bn]);
    const uint32_t sB1 = sptr(&Bs[1][bk][bn]);

    // prologue: stage 0
    cp16(sA0, aG, asz);      cp16(sA0 + 16, aG + 4, asz);
    cp16(sB0, bG, 16);       cp16(sB0 + 16, bG + 4, 16);
    asm volatile("cp.async.commit_group;");

    for (int it = 0; it < NITER; it++) {
        const int buf = it & 1;
        if (it + 1 < NITER) {
            const float* a0 = aG + (it + 1) * GK;
            const float* b0 = bG + (size_t)(it + 1) * GK * FOUT;
            const uint32_t sa = buf ? sA0 : sA1;
            const uint32_t sb = buf ? sB0 : sB1;
            cp16(sa, a0, asz);   cp16(sa + 16, a0 + 4, asz);
            cp16(sb, b0, 16);    cp16(sb + 16, b0 + 4, 16);
        }
        asm volatile("cp.async.commit_group;");
        asm volatile("cp.async.wait_group 1;");
        __syncthreads();

#pragma unroll
        for (int ks = 0; ks < 2; ks++) {
            const int kb = ks * 8;
            uint32_t afr[2][4], bfr[8][2];
#pragma unroll
            for (int mi = 0; mi < 2; mi++) {
                const int m = wm + mi * 16;
                afr[mi][0] = f2tf32(As[buf][m + g][kb + tg]);
                afr[mi][1] = f2tf32(As[buf][m + g + 8][kb + tg]);
                afr[mi][2] = f2tf32(As[buf][m + g][kb + tg + 4]);
                afr[mi][3] = f2tf32(As[buf][m + g + 8][kb + tg + 4]);
            }
#pragma unroll
            for (int ni = 0; ni < 8; ni++) {
                const int n = wn + ni * 8 + g;
                bfr[ni][0] = f2tf32(Bs[buf][kb + tg][n]);
                bfr[ni][1] = f2tf32(Bs[buf][kb + tg + 4][n]);
            }
#pragma unroll
            for (int mi = 0; mi < 2; mi++)
#pragma unroll
                for (int ni = 0; ni < 8; ni++)
                    mma_tf32(acc[mi][ni], afr[mi], bfr[ni]);
        }
        __syncthreads();
    }

    // Epilogue: fp16 store (2 cols per __half2)
#pragma unroll
    for (int mi = 0; mi < 2; mi++) {
        const int r0 = block_row + wm + mi * 16 + g;
#pragma unroll
        for (int ni = 0; ni < 8; ni++) {
            const int c = wn + ni * 8 + tg * 2;
            if (r0 < N_NODES)
                *(__half2*)(g_pre + (size_t)r0 * FOUT + c) =
                    __floats2half2_rn(acc[mi][ni][0], acc[mi][ni][1]);
            if (r0 + 8 < N_NODES)
                *(__half2*)(g_pre + (size_t)(r0 + 8) * FOUT + c) =
                    __floats2half2_rn(acc[mi][ni][2], acc[mi][ni][3]);
        }
    }
}

// ---------------------------------------------------------------------------
// CSR build
// ---------------------------------------------------------------------------
__global__ void zero_counts_kernel() {
    int i = blockIdx.x * blockDim.x + threadIdx.x;
    if (i < 2 * N_NODES) ((int*)g_counts)[i] = 0;
}

// histogram: 4 edges per thread (grid.y = branch)
__global__ __launch_bounds__(256) void hist_kernel(const int* __restrict__ idx0,
                                                   const int* __restrict__ idx1, int E) {
    const int* idx = blockIdx.y ? idx1 : idx0;
    const int stride = gridDim.x * blockDim.x;
    int t = blockIdx.x * blockDim.x + threadIdx.x;
    int rows[4];
    bool ok[4];
#pragma unroll
    for (int r = 0; r < 4; r++) {
        int e = t + r * stride;
        ok[r] = (e < E);
        if (ok[r]) {
            rows[r] = idx[e];
            int col = idx[E + e];
            if ((unsigned)rows[r] >= N_NODES || (unsigned)col >= N_NODES) ok[r] = false;
        }
    }
#pragma unroll
    for (int r = 0; r < 4; r++)
        if (ok[r]) atomicAdd(&g_counts[blockIdx.y][rows[r]], 1);
}

// exclusive scan over 50000 bins; one block per branch
__global__ __launch_bounds__(1024) void scan_kernel() {
    const int b = blockIdx.x;
    const int t = threadIdx.x;
    const int ITEMS = (N_NODES + 1023) / 1024;
    const int start = t * ITEMS;

    int local = 0;
    for (int i = 0; i < ITEMS; i++) {
        int bin = start + i;
        if (bin < N_NODES) local += g_counts[b][bin];
    }
    __shared__ int s[1024];
    s[t] = local;
    __syncthreads();
    for (int off = 1; off < 1024; off <<= 1) {
        int v = (t >= off) ? s[t - off] : 0;
        __syncthreads();
        s[t] += v;
        __syncthreads();
    }
    int run = s[t] - local;
    for (int i = 0; i < ITEMS; i++) {
        int bin = start + i;
        if (bin < N_NODES) {
            g_rowstart[b][bin] = run;
            g_cursor[b][bin] = run;
            run += g_counts[b][bin];
        }
    }
    if (t == 1023) g_rowstart[b][N_NODES] = s[1023];
}

// scatter: 4 edges per thread, batched load -> batched atomic -> batched store
__global__ __launch_bounds__(256) void scatter_kernel(const int* __restrict__ idx0,
                                                      const float* __restrict__ v0,
                                                      const int* __restrict__ idx1,
                                                      const float* __restrict__ v1, int E) {
    const int b = blockIdx.y;
    const int* idx = b ? idx1 : idx0;
    const float* vals = b ? v1 : v0;
    const int stride = gridDim.x * blockDim.x;
    int t = blockIdx.x * blockDim.x + threadIdx.x;

    int rows[4], cols[4], pos[4];
    float vv[4];
    bool ok[4];
#pragma unroll
    for (int r = 0; r < 4; r++) {
        int e = t + r * stride;
        ok[r] = (e < E);
        if (ok[r]) {
            rows[r] = idx[e];
            cols[r] = idx[E + e];
            vv[r] = vals[e];
            if ((unsigned)rows[r] >= N_NODES || (unsigned)cols[r] >= N_NODES) ok[r] = false;
        }
    }
#pragma unroll
    for (int r = 0; r < 4; r++)
        if (ok[r]) pos[r] = atomicAdd(&g_cursor[b][rows[r]], 1);
#pragma unroll
    for (int r = 0; r < 4; r++)
        if (ok[r] && pos[r] < MAXE)
            g_edges[b][pos[r]] = make_int2(cols[r], __float_as_int(vv[r]));
}

// ---------------------------------------------------------------------------
// Gather SpMM (fp16 pre) + fused bias + ReLU. One warp per (branch,row).
// Lane l handles cols [4l, 4l+4): one uint2 (4 halfs) per edge gather.
// ---------------------------------------------------------------------------
__global__ __launch_bounds__(256) void spmm_csr_kernel(float* __restrict__ out,
                                                       const float* __restrict__ bias) {
    const int b = blockIdx.y;
    const int warp = threadIdx.x >> 5;
    const int lane = threadIdx.x & 31;
    const int row = blockIdx.x * 8 + warp;
    if (row >= N_NODES) return;

    const int beg = g_rowstart[b][row];
    const int end = g_rowstart[b][row + 1];
    const int2* __restrict__ edges = g_edges[b];
    const uint2* __restrict__ pre2 = (const uint2*)g_pre;   // 32 uint2 per row

    float4 acc = make_float4(0.f, 0.f, 0.f, 0.f);
    int e = beg;
    for (; e + 4 <= end; e += 4) {
        int2 e0 = edges[e], e1 = edges[e + 1], e2 = edges[e + 2], e3 = edges[e + 3];
        uint2 m0 = pre2[(size_t)e0.x * 32 + lane];
        uint2 m1 = pre2[(size_t)e1.x * 32 + lane];
        uint2 m2 = pre2[(size_t)e2.x * 32 + lane];
        uint2 m3 = pre2[(size_t)e3.x * 32 + lane];
        float v0 = __int_as_float(e0.y), v1 = __int_as_float(e1.y);
        float v2 = __int_as_float(e2.y), v3 = __int_as_float(e3.y);
        float2 a0 = __half22float2(*(__half2*)&m0.x), b0 = __half22float2(*(__half2*)&m0.y);
        float2 a1 = __half22float2(*(__half2*)&m1.x), b1 = __half22float2(*(__half2*)&m1.y);
        float2 a2 = __half22float2(*(__half2*)&m2.x), b2 = __half22float2(*(__half2*)&m2.y);
        float2 a3 = __half22float2(*(__half2*)&m3.x), b3 = __half22float2(*(__half2*)&m3.y);
        acc.x += v0 * a0.x + v1 * a1.x + v2 * a2.x + v3 * a3.x;
        acc.y += v0 * a0.y + v1 * a1.y + v2 * a2.y + v3 * a3.y;
        acc.z += v0 * b0.x + v1 * b1.x + v2 * b2.x + v3 * b3.x;
        acc.w += v0 * b0.y + v1 * b1.y + v2 * b2.y + v3 * b3.y;
    }
    for (; e < end; e++) {
        int2 ed = edges[e];
        float v = __int_as_float(ed.y);
        uint2 m = pre2[(size_t)ed.x * 32 + lane];
        float2 a = __half22float2(*(__half2*)&m.x), bb = __half22float2(*(__half2*)&m.y);
        acc.x += v * a.x; acc.y += v * a.y; acc.z += v * bb.x; acc.w += v * bb.y;
    }

    float4 bb = ((const float4*)bias)[lane];
    acc.x = fmaxf(acc.x + bb.x, 0.f);
    acc.y = fmaxf(acc.y + bb.y, 0.f);
    acc.z = fmaxf(acc.z + bb.z, 0.f);
    acc.w = fmaxf(acc.w + bb.w, 0.f);

    float4* orow = (float4*)(out + ((size_t)b * N_NODES + row) * FOUT);
    orow[lane] = acc;
}

// ---------------------------------------------------------------------------
// Launch: [default stream: csr-build] || [side stream: gemm] -> join -> spmm
// Stream/events created once (host resources only; no device memory).
// ---------------------------------------------------------------------------
extern "C" void kernel_launch(void* const* d_in, const int* in_sizes, int n_in,
                              void* d_out, int out_size) {
    const float* x     = (const float*)d_in[0];
    const int*   sidx  = (const int*)d_in[1];
    const float* svals = (const float*)d_in[2];
    const int*   oidx  = (const int*)d_in[3];
    const float* ovals = (const float*)d_in[4];
    const float* W     = (const float*)d_in[5];
    const float* bias  = (const float*)d_in[6];
    float* out = (float*)d_out;

    int E = in_sizes[2];
    if (E > MAXE) E = MAXE;

    static cudaStream_t s2 = nullptr;
    static cudaEvent_t ev_fork = nullptr, ev_gemm = nullptr;
    if (!s2) {
        cudaStreamCreateWithFlags(&s2, cudaStreamNonBlocking);
        cudaEventCreateWithFlags(&ev_fork, cudaEventDisableTiming);
        cudaEventCreateWithFlags(&ev_gemm, cudaEventDisableTiming);
    }

    // Fork: GEMM on side stream (independent of CSR build)
    cudaEventRecord(ev_fork, 0);
    cudaStreamWaitEvent(s2, ev_fork, 0);
    gemm_tf32_db<<<(N_NODES + GM - 1) / GM, 256, 0, s2>>>(x, W);
    cudaEventRecord(ev_gemm, s2);

    // CSR build on default stream, overlapped with GEMM
    zero_counts_kernel<<<(2 * N_NODES + 255) / 256, 256>>>();
    dim3 eg4((E + 1023) / 1024, 2);
    hist_kernel<<<eg4, 256>>>(sidx, oidx, E);
    scan_kernel<<<2, 1024>>>();
    scatter_kernel<<<eg4, 256>>>(sidx, svals, oidx, ovals, E);

    // Join, then gather-SpMM with fused bias+ReLU
    cudaStreamWaitEvent(0, ev_gemm, 0);
    dim3 sg((N_NODES + 7) / 8, 2);
    spmm_csr_kernel<<<sg, 256>>>(out, bias);
}

// round 14
// speedup vs baseline: 2.1354x; 2.1354x over previous
#include <cuda_runtime.h>
#include <cuda_fp16.h>
#include <cstdint>

#define N_NODES 50000
#define FIN 512
#define FOUT 128
#define MAXE 1000000

#define SCHUNK 512
#define NCHUNK ((N_NODES + SCHUNK - 1) / SCHUNK)   // 98

// Static device scratch (no allocation anywhere):
__device__ __half g_pre[(size_t)N_NODES * FOUT];         // fp16 pre_sup, 12.8 MB
__device__ int   g_counts[2][N_NODES];
__device__ int   g_rowstart[2][N_NODES + 1];
__device__ int   g_cursor[2][N_NODES];
__device__ int   g_chunksum[2][NCHUNK];                  // per-chunk totals
__device__ int   g_chunkoff[2][NCHUNK];                  // per-chunk exclusive offsets
__device__ int2  g_edges[2][MAXE];                       // packed (col, val-bits)

// ---------------------------------------------------------------------------
// helpers
// ---------------------------------------------------------------------------
__device__ __forceinline__ uint32_t f2tf32(float f) {
    uint32_t u;
    asm("cvt.rna.tf32.f32 %0, %1;" : "=r"(u) : "f"(f));
    return u;
}

__device__ __forceinline__ void mma_tf32(float* d, const uint32_t* a, const uint32_t* b) {
    asm("mma.sync.aligned.m16n8k8.row.col.f32.tf32.tf32.f32 "
        "{%0,%1,%2,%3}, {%4,%5,%6,%7}, {%8,%9}, {%0,%1,%2,%3};"
        : "+f"(d[0]), "+f"(d[1]), "+f"(d[2]), "+f"(d[3])
        : "r"(a[0]), "r"(a[1]), "r"(a[2]), "r"(a[3]), "r"(b[0]), "r"(b[1]));
}

__device__ __forceinline__ uint32_t sptr(const void* p) {
    return (uint32_t)__cvta_generic_to_shared(p);
}

__device__ __forceinline__ void cp16(uint32_t s, const void* g, int src_sz) {
    asm volatile("cp.async.ca.shared.global [%0], [%1], 16, %2;"
                 :: "r"(s), "l"(g), "r"(src_sz));
}

// ---------------------------------------------------------------------------
// tf32 GEMM, cp.async double-buffered (R11-proven), fp16 output.
// ---------------------------------------------------------------------------
#define GM 128
#define GK 16
#define ASTR 20
#define BSTR 136
#define NITER (FIN / GK)   // 32

__global__ __launch_bounds__(256, 2) void gemm_tf32_db(const float* __restrict__ A,
                                                       const float* __restrict__ B) {
    __shared__ float As[2][GM][ASTR];
    __shared__ float Bs[2][GK][BSTR];

    const int tid = threadIdx.x;
    const int w = tid >> 5, l = tid & 31;
    const int wm = (w >> 1) * 32;
    const int wn = (w & 1) * 64;
    const int g = l >> 2, tg = l & 3;
    const int block_row = blockIdx.x * GM;

    float acc[2][8][4];
#pragma unroll
    for (int mi = 0; mi < 2; mi++)
#pragma unroll
        for (int ni = 0; ni < 8; ni++)
#pragma unroll
            for (int q = 0; q < 4; q++) acc[mi][ni][q] = 0.f;

    const int am = tid >> 1;
    const int ak = (tid & 1) * 8;
    const int arow = block_row + am;
    const int asz = (arow < N_NODES) ? 16 : 0;
    const float* aG = A + (size_t)arow * FIN + ak;
    const int bk = tid >> 4;
    const int bn = (tid & 15) * 8;
    const float* bG = B + (size_t)bk * FOUT + bn;

    const uint32_t sA0 = sptr(&As[0][am][ak]);
    const uint32_t sA1 = sptr(&As[1][am][ak]);
    const uint32_t sB0 = sptr(&Bs[0][bk][bn]);
    const uint32_t sB1 = sptr(&Bs[1][bk][bn]);

    cp16(sA0, aG, asz);      cp16(sA0 + 16, aG + 4, asz);
    cp16(sB0, bG, 16);       cp16(sB0 + 16, bG + 4, 16);
    asm volatile("cp.async.commit_group;");

    for (int it = 0; it < NITER; it++) {
        const int buf = it & 1;
        if (it + 1 < NITER) {
            const float* a0 = aG + (it + 1) * GK;
            const float* b0 = bG + (size_t)(it + 1) * GK * FOUT;
            const uint32_t sa = buf ? sA0 : sA1;
            const uint32_t sb = buf ? sB0 : sB1;
            cp16(sa, a0, asz);   cp16(sa + 16, a0 + 4, asz);
            cp16(sb, b0, 16);    cp16(sb + 16, b0 + 4, 16);
        }
        asm volatile("cp.async.commit_group;");
        asm volatile("cp.async.wait_group 1;");
        __syncthreads();

#pragma unroll
        for (int ks = 0; ks < 2; ks++) {
            const int kb = ks * 8;
            uint32_t afr[2][4], bfr[8][2];
#pragma unroll
            for (int mi = 0; mi < 2; mi++) {
                const int m = wm + mi * 16;
                afr[mi][0] = f2tf32(As[buf][m + g][kb + tg]);
                afr[mi][1] = f2tf32(As[buf][m + g + 8][kb + tg]);
                afr[mi][2] = f2tf32(As[buf][m + g][kb + tg + 4]);
                afr[mi][3] = f2tf32(As[buf][m + g + 8][kb + tg + 4]);
            }
#pragma unroll
            for (int ni = 0; ni < 8; ni++) {
                const int n = wn + ni * 8 + g;
                bfr[ni][0] = f2tf32(Bs[buf][kb + tg][n]);
                bfr[ni][1] = f2tf32(Bs[buf][kb + tg + 4][n]);
            }
#pragma unroll
            for (int mi = 0; mi < 2; mi++)
#pragma unroll
                for (int ni = 0; ni < 8; ni++)
                    mma_tf32(acc[mi][ni], afr[mi], bfr[ni]);
        }
        __syncthreads();
    }

#pragma unroll
    for (int mi = 0; mi < 2; mi++) {
        const int r0 = block_row + wm + mi * 16 + g;
#pragma unroll
        for (int ni = 0; ni < 8; ni++) {
            const int c = wn + ni * 8 + tg * 2;
            if (r0 < N_NODES)
                *(__half2*)(g_pre + (size_t)r0 * FOUT + c) =
                    __floats2half2_rn(acc[mi][ni][0], acc[mi][ni][1]);
            if (r0 + 8 < N_NODES)
                *(__half2*)(g_pre + (size_t)(r0 + 8) * FOUT + c) =
                    __floats2half2_rn(acc[mi][ni][2], acc[mi][ni][3]);
        }
    }
}

// ---------------------------------------------------------------------------
// CSR build
// ---------------------------------------------------------------------------
__global__ void zero_counts_kernel() {
    int i = blockIdx.x * blockDim.x + threadIdx.x;
    if (i < 2 * N_NODES) ((int*)g_counts)[i] = 0;
}

// histogram: 4 edges per thread (grid.y = branch)
__global__ __launch_bounds__(256) void hist_kernel(const int* __restrict__ idx0,
                                                   const int* __restrict__ idx1, int E) {
    const int* idx = blockIdx.y ? idx1 : idx0;
    const int stride = gridDim.x * blockDim.x;
    int t = blockIdx.x * blockDim.x + threadIdx.x;
    int rows[4];
    bool ok[4];
#pragma unroll
    for (int r = 0; r < 4; r++) {
        int e = t + r * stride;
        ok[r] = (e < E);
        if (ok[r]) {
            rows[r] = idx[e];
            int col = idx[E + e];
            if ((unsigned)rows[r] >= N_NODES || (unsigned)col >= N_NODES) ok[r] = false;
        }
    }
#pragma unroll
    for (int r = 0; r < 4; r++)
        if (ok[r]) atomicAdd(&g_counts[blockIdx.y][rows[r]], 1);
}

// --- hierarchical scan, stage 1: per-chunk block scan (196 blocks x 512) ---
__global__ __launch_bounds__(SCHUNK) void scan1_kernel() {
    const int b = blockIdx.y;
    const int t = threadIdx.x;
    const int bin = blockIdx.x * SCHUNK + t;

    int v = (bin < N_NODES) ? g_counts[b][bin] : 0;
    __shared__ int s[SCHUNK];
    s[t] = v;
    __syncthreads();
#pragma unroll
    for (int off = 1; off < SCHUNK; off <<= 1) {
        int u = (t >= off) ? s[t - off] : 0;
        __syncthreads();
        s[t] += u;
        __syncthreads();
    }
    if (bin < N_NODES) g_rowstart[b][bin] = s[t] - v;   // local exclusive
    if (t == SCHUNK - 1) g_chunksum[b][blockIdx.x] = s[t];
}

// stage 2: scan the 98 chunk totals per branch (2 blocks x 128)
__global__ __launch_bounds__(128) void scan2_kernel() {
    const int b = blockIdx.x;
    const int t = threadIdx.x;
    int v = (t < NCHUNK) ? g_chunksum[b][t] : 0;
    __shared__ int s[128];
    s[t] = v;
    __syncthreads();
#pragma unroll
    for (int off = 1; off < 128; off <<= 1) {
        int u = (t >= off) ? s[t - off] : 0;
        __syncthreads();
        s[t] += u;
        __syncthreads();
    }
    if (t < NCHUNK) g_chunkoff[b][t] = s[t] - v;        // exclusive
    if (t == NCHUNK - 1) g_rowstart[b][N_NODES] = s[t];  // grand total
}

// stage 3: add chunk offsets, finalize rowstart + cursor (196 blocks x 512)
__global__ __launch_bounds__(SCHUNK) void scan3_kernel() {
    const int b = blockIdx.y;
    const int bin = blockIdx.x * SCHUNK + threadIdx.x;
    if (bin < N_NODES) {
        int r = g_rowstart[b][bin] + g_chunkoff[b][blockIdx.x];
        g_rowstart[b][bin] = r;
        g_cursor[b][bin] = r;
    }
}

// scatter: 4 edges per thread, batched load -> batched atomic -> batched store
__global__ __launch_bounds__(256) void scatter_kernel(const int* __restrict__ idx0,
                                                      const float* __restrict__ v0,
                                                      const int* __restrict__ idx1,
                                                      const float* __restrict__ v1, int E) {
    const int b = blockIdx.y;
    const int* idx = b ? idx1 : idx0;
    const float* vals = b ? v1 : v0;
    const int stride = gridDim.x * blockDim.x;
    int t = blockIdx.x * blockDim.x + threadIdx.x;

    int rows[4], cols[4], pos[4];
    float vv[4];
    bool ok[4];
#pragma unroll
    for (int r = 0; r < 4; r++) {
        int e = t + r * stride;
        ok[r] = (e < E);
        if (ok[r]) {
            rows[r] = idx[e];
            cols[r] = idx[E + e];
            vv[r] = vals[e];
            if ((unsigned)rows[r] >= N_NODES || (unsigned)cols[r] >= N_NODES) ok[r] = false;
        }
    }
#pragma unroll
    for (int r = 0; r < 4; r++)
        if (ok[r]) pos[r] = atomicAdd(&g_cursor[b][rows[r]], 1);
#pragma unroll
    for (int r = 0; r < 4; r++)
        if (ok[r] && pos[r] < MAXE)
            g_edges[b][pos[r]] = make_int2(cols[r], __float_as_int(vv[r]));
}

// ---------------------------------------------------------------------------
// Gather SpMM (fp16 pre) + fused bias + ReLU. One warp per (branch,row).
// ---------------------------------------------------------------------------
__global__ __launch_bounds__(256) void spmm_csr_kernel(float* __restrict__ out,
                                                       const float* __restrict__ bias) {
    const int b = blockIdx.y;
    const int warp = threadIdx.x >> 5;
    const int lane = threadIdx.x & 31;
    const int row = blockIdx.x * 8 + warp;
    if (row >= N_NODES) return;

    const int beg = g_rowstart[b][row];
    const int end = g_rowstart[b][row + 1];
    const int2* __restrict__ edges = g_edges[b];
    const uint2* __restrict__ pre2 = (const uint2*)g_pre;

    float4 acc = make_float4(0.f, 0.f, 0.f, 0.f);
    int e = beg;
    for (; e + 4 <= end; e += 4) {
        int2 e0 = edges[e], e1 = edges[e + 1], e2 = edges[e + 2], e3 = edges[e + 3];
        uint2 m0 = pre2[(size_t)e0.x * 32 + lane];
        uint2 m1 = pre2[(size_t)e1.x * 32 + lane];
        uint2 m2 = pre2[(size_t)e2.x * 32 + lane];
        uint2 m3 = pre2[(size_t)e3.x * 32 + lane];
        float v0 = __int_as_float(e0.y), v1 = __int_as_float(e1.y);
        float v2 = __int_as_float(e2.y), v3 = __int_as_float(e3.y);
        float2 a0 = __half22float2(*(__half2*)&m0.x), b0 = __half22float2(*(__half2*)&m0.y);
        float2 a1 = __half22float2(*(__half2*)&m1.x), b1 = __half22float2(*(__half2*)&m1.y);
        float2 a2 = __half22float2(*(__half2*)&m2.x), b2 = __half22float2(*(__half2*)&m2.y);
        float2 a3 = __half22float2(*(__half2*)&m3.x), b3 = __half22float2(*(__half2*)&m3.y);
        acc.x += v0 * a0.x + v1 * a1.x + v2 * a2.x + v3 * a3.x;
        acc.y += v0 * a0.y + v1 * a1.y + v2 * a2.y + v3 * a3.y;
        acc.z += v0 * b0.x + v1 * b1.x + v2 * b2.x + v3 * b3.x;
        acc.w += v0 * b0.y + v1 * b1.y + v2 * b2.y + v3 * b3.y;
    }
    for (; e < end; e++) {
        int2 ed = edges[e];
        float v = __int_as_float(ed.y);
        uint2 m = pre2[(size_t)ed.x * 32 + lane];
        float2 a = __half22float2(*(__half2*)&m.x), bb = __half22float2(*(__half2*)&m.y);
        acc.x += v * a.x; acc.y += v * a.y; acc.z += v * bb.x; acc.w += v * bb.y;
    }

    float4 bb = ((const float4*)bias)[lane];
    acc.x = fmaxf(acc.x + bb.x, 0.f);
    acc.y = fmaxf(acc.y + bb.y, 0.f);
    acc.z = fmaxf(acc.z + bb.z, 0.f);
    acc.w = fmaxf(acc.w + bb.w, 0.f);

    float4* orow = (float4*)(out + ((size_t)b * N_NODES + row) * FOUT);
    orow[lane] = acc;
}

// ---------------------------------------------------------------------------
// Launch: [default: csr-build] || [side: gemm] -> join -> spmm
// ---------------------------------------------------------------------------
extern "C" void kernel_launch(void* const* d_in, const int* in_sizes, int n_in,
                              void* d_out, int out_size) {
    const float* x     = (const float*)d_in[0];
    const int*   sidx  = (const int*)d_in[1];
    const float* svals = (const float*)d_in[2];
    const int*   oidx  = (const int*)d_in[3];
    const float* ovals = (const float*)d_in[4];
    const float* W     = (const float*)d_in[5];
    const float* bias  = (const float*)d_in[6];
    float* out = (float*)d_out;

    int E = in_sizes[2];
    if (E > MAXE) E = MAXE;

    static cudaStream_t s2 = nullptr;
    static cudaEvent_t ev_fork = nullptr, ev_gemm = nullptr;
    if (!s2) {
        cudaStreamCreateWithFlags(&s2, cudaStreamNonBlocking);
        cudaEventCreateWithFlags(&ev_fork, cudaEventDisableTiming);
        cudaEventCreateWithFlags(&ev_gemm, cudaEventDisableTiming);
    }

    // Fork: GEMM on side stream (independent of CSR build)
    cudaEventRecord(ev_fork, 0);
    cudaStreamWaitEvent(s2, ev_fork, 0);
    gemm_tf32_db<<<(N_NODES + GM - 1) / GM, 256, 0, s2>>>(x, W);
    cudaEventRecord(ev_gemm, s2);

    // CSR build on default stream, overlapped with GEMM
    zero_counts_kernel<<<(2 * N_NODES + 255) / 256, 256>>>();
    dim3 eg4((E + 1023) / 1024, 2);
    hist_kernel<<<eg4, 256>>>(sidx, oidx, E);
    dim3 cg(NCHUNK, 2);
    scan1_kernel<<<cg, SCHUNK>>>();
    scan2_kernel<<<2, 128>>>();
    scan3_kernel<<<cg, SCHUNK>>>();
    scatter_kernel<<<eg4, 256>>>(sidx, svals, oidx, ovals, E);

    // Join, then gather-SpMM with fused bias+ReLU
    cudaStreamWaitEvent(0, ev_gemm, 0);
    dim3 sg((N_NODES + 7) / 8, 2);
    spmm_csr_kernel<<<sg, 256>>>(out, bias);
}